// round 9
// baseline (speedup 1.0000x reference)
#include <cuda_runtime.h>

// Warp-autonomous, fused-span version: each warp owns 64 consecutive rows
// = one contiguous 6400B span. ONE cp.async.bulk load fills the warp's smem
// span; after the mbarrier flips, ONE cp.async.bulk store streams it back
// out as the output (identity when no reflection coefficient clips;
// BOUND = 1-1e-16 rounds to 1.0f). Each lane runs TWO independent
// division-free Levinson detector chains (rows lane and lane+32),
// interleaved stage-by-stage for ILP=2 against the RCP->FMA critical path.
// Clipped rows (rare to nonexistent) overwrite themselves after
// wait_group-ordering behind the bulk store.

#define M 24
#define ROW 25
#define WARPS_PER_BLK 8
#define THREADS (WARPS_PER_BLK * 32)
#define ROWS_PER_WARP 64
#define FLOATS_PER_WARP (ROWS_PER_WARP * ROW)          // 1600
#define BYTES_PER_WARP  (FLOATS_PER_WARP * 4)          // 6400 (16B multiple)

__device__ __forceinline__ void mbar_wait(unsigned mb, unsigned parity)
{
    asm volatile(
        "{\n\t"
        ".reg .pred P1;\n\t"
        "LAB_WAIT%=:\n\t"
        "mbarrier.try_wait.parity.acquire.cta.shared::cta.b64 P1, [%0], %1, 0x989680;\n\t"
        "@P1 bra LAB_DONE%=;\n\t"
        "bra LAB_WAIT%=;\n\t"
        "LAB_DONE%=:\n\t"
        "}"
        :: "r"(mb), "r"(parity) : "memory");
}

// Single-row division-free detector (tail path).
__device__ __forceinline__ float detector(const float* __restrict__ row)
{
    float u[M];
    #pragma unroll
    for (int i = 0; i < M; ++i) u[i] = row[i + 1];
    float D = 1.0f, maxa = 0.0f;
    #pragma unroll
    for (int m = M; m >= 2; --m) {
        float um = u[m - 1];
        float k  = um * __fdividef(1.0f, D);
        maxa = fmaxf(maxa, fabsf(k));
        D = fmaf(-k, um, D);
        #pragma unroll
        for (int i = 0; 2 * i <= m - 2; ++i) {
            int j = m - 2 - i;
            float ui = u[i], uj = u[j];
            if (i < j) {
                u[i] = fmaf(-k, uj, ui);
                u[j] = fmaf(-k, ui, uj);
            } else {
                u[i] = fmaf(-k, ui, ui);
            }
        }
    }
    return fmaxf(maxa, fabsf(u[0] * __fdividef(1.0f, D)));
}

// Dual-row detector: two independent chains interleaved per stage (ILP=2).
__device__ __forceinline__ void detector2(const float* __restrict__ rowA,
                                          const float* __restrict__ rowB,
                                          float& outA, float& outB)
{
    float uA[M], uB[M];
    #pragma unroll
    for (int i = 0; i < M; ++i) { uA[i] = rowA[i + 1]; uB[i] = rowB[i + 1]; }

    float DA = 1.0f, DB = 1.0f, mA = 0.0f, mB = 0.0f;
    #pragma unroll
    for (int m = M; m >= 2; --m) {
        float umA = uA[m - 1],            umB = uB[m - 1];
        float kA  = umA * __fdividef(1.0f, DA);
        float kB  = umB * __fdividef(1.0f, DB);
        mA = fmaxf(mA, fabsf(kA));        mB = fmaxf(mB, fabsf(kB));
        DA = fmaf(-kA, umA, DA);          DB = fmaf(-kB, umB, DB);
        #pragma unroll
        for (int i = 0; 2 * i <= m - 2; ++i) {
            int j = m - 2 - i;
            float aI = uA[i], aJ = uA[j];
            float bI = uB[i], bJ = uB[j];
            if (i < j) {
                uA[i] = fmaf(-kA, aJ, aI);  uB[i] = fmaf(-kB, bJ, bI);
                uA[j] = fmaf(-kA, aI, aJ);  uB[j] = fmaf(-kB, bI, bJ);
            } else {
                uA[i] = fmaf(-kA, aI, aI);  uB[i] = fmaf(-kB, bI, bI);
            }
        }
    }
    outA = fmaxf(mA, fabsf(uA[0] * __fdividef(1.0f, DA)));
    outB = fmaxf(mB, fabsf(uB[0] * __fdividef(1.0f, DB)));
}

// Exact per-row path: true divides, clamp, upward recursion, overwrite row.
__device__ __noinline__ void fixup_row(const float* __restrict__ srow,
                                       float* __restrict__ orow)
{
    float c[M];
    #pragma unroll
    for (int i = 0; i < M; ++i) c[i] = srow[i + 1];

    #pragma unroll
    for (int m = M; m >= 2; --m) {
        float k   = c[m - 1];
        float inv = __fdividef(1.0f, 1.0f - k * k);
        #pragma unroll
        for (int i = 0; 2 * i <= m - 2; ++i) {
            int j = m - 2 - i;
            float ci = c[i], cj = c[j];
            if (i < j) {
                c[i] = fmaf(-k, cj, ci) * inv;
                c[j] = fmaf(-k, ci, cj) * inv;
            } else {
                c[i] = fmaf(-k, ci, ci) * inv;
            }
        }
    }
    #pragma unroll
    for (int i = 0; i < M; ++i)
        c[i] = fminf(fmaxf(c[i], -1.0f), 1.0f);

    #pragma unroll
    for (int m = 2; m <= M; ++m) {
        float km = c[m - 1];
        #pragma unroll
        for (int i = 0; 2 * i <= m - 2; ++i) {
            int j = m - 2 - i;
            float ci = c[i], cj = c[j];
            if (i < j) {
                c[i] = fmaf(km, cj, ci);
                c[j] = fmaf(km, ci, cj);
            } else {
                c[i] = fmaf(km, ci, ci);
            }
        }
    }
    #pragma unroll
    for (int i = 0; i < M; ++i) orow[i + 1] = c[i];
    // orow[0] (gain K) already correct from the bulk copy
}

__global__ __launch_bounds__(THREADS, 4)
void lpc_stability_kernel(const float* __restrict__ in, float* __restrict__ out, int B)
{
    __shared__ float s[WARPS_PER_BLK * FLOATS_PER_WARP];   // 51.2 KB
    __shared__ unsigned long long mbar[WARPS_PER_BLK];

    const int wid  = threadIdx.x >> 5;
    const int lane = threadIdx.x & 31;
    const long long wg = (long long)blockIdx.x * WARPS_PER_BLK + wid;
    const long long rbase = wg * ROWS_PER_WARP;
    if (rbase >= B) return;                    // warp-uniform exit
    const int nrows = min((long long)ROWS_PER_WARP, B - rbase);

    float* ws = s + wid * FLOATS_PER_WARP;
    const float* gsrc = in  + rbase * ROW;
    float*       gdst = out + rbase * ROW;
    unsigned s_addr = (unsigned)__cvta_generic_to_shared(ws);
    unsigned mb     = (unsigned)__cvta_generic_to_shared(&mbar[wid]);

    if (nrows == ROWS_PER_WARP) {
        // ---- one async load of this warp's 6400B span ----
        if (lane == 0) {
            asm volatile("mbarrier.init.shared.b64 [%0], %1;"
                         :: "r"(mb), "r"(1) : "memory");
            asm volatile("mbarrier.arrive.expect_tx.shared.b64 _, [%0], %1;"
                         :: "r"(mb), "r"((unsigned)BYTES_PER_WARP) : "memory");
            asm volatile("cp.async.bulk.shared::cluster.global.mbarrier::complete_tx::bytes "
                         "[%0], [%1], %2, [%3];"
                         :: "r"(s_addr), "l"(gsrc), "r"((unsigned)BYTES_PER_WARP), "r"(mb)
                         : "memory");
        }
        __syncwarp();              // init visible before other lanes wait
        mbar_wait(mb, 0);          // acquire: smem span ready

        // ---- one async out-copy (identity result) on the TMA engine ----
        if (lane == 0) {
            asm volatile("fence.proxy.async.shared::cta;" ::: "memory");
            asm volatile("cp.async.bulk.global.shared::cta.bulk_group [%0], [%1], %2;"
                         :: "l"(gdst), "r"(s_addr), "r"((unsigned)BYTES_PER_WARP)
                         : "memory");
            asm volatile("cp.async.bulk.commit_group;" ::: "memory");
        }

        // ---- dual detector, interleaved chains (overlaps the bulk store) --
        const float* rowA = ws + lane * ROW;
        const float* rowB = ws + (lane + 32) * ROW;
        float mA, mB;
        detector2(rowA, rowB, mA, mB);

        unsigned clip = __ballot_sync(0xffffffffu,
                                      !(mA <= 1.0f) || !(mB <= 1.0f));
        if (clip) {
            if (lane == 0)
                asm volatile("cp.async.bulk.wait_group 0;" ::: "memory");
            __syncwarp();          // fixup STGs ordered after the bulk store
            if (!(mA <= 1.0f))
                fixup_row(rowA, gdst + (long long)lane * ROW);
            if (!(mB <= 1.0f))
                fixup_row(rowB, gdst + (long long)(lane + 32) * ROW);
        }
    } else {
        // ---- generic tail (not hit for B = 2M): scalar copy + detect ----
        int nelem = nrows * ROW;
        for (int idx = lane; idx < nelem; idx += 32) {
            float v = gsrc[idx];
            gdst[idx] = v;
            ws[idx] = v;
        }
        __syncwarp();
        for (int r = lane; r < nrows; r += 32) {
            const float* row = ws + r * ROW;
            if (!(detector(row) <= 1.0f))
                fixup_row(row, gdst + (long long)r * ROW);
        }
    }
}

extern "C" void kernel_launch(void* const* d_in, const int* in_sizes, int n_in,
                              void* d_out, int out_size)
{
    const float* a = (const float*)d_in[0];
    float* out = (float*)d_out;
    int B = in_sizes[0] / ROW;
    long long nwarps = ((long long)B + ROWS_PER_WARP - 1) / ROWS_PER_WARP;
    int grid = (int)((nwarps + WARPS_PER_BLK - 1) / WARPS_PER_BLK);
    lpc_stability_kernel<<<grid, THREADS>>>(a, out, B);
}